// round 1
// baseline (speedup 1.0000x reference)
#include <cuda_runtime.h>
#include <cstdint>
#include <math.h>

// Problem constants
#define B_    32
#define L_    2048
#define I_    256
#define H_    512
#define HX    768      // H + I (weight row length)
#define N3    1536     // 3*H combined gate columns (z | r | w)
#define NCTA  128
#define NTHR  256
#define HS    516      // padded row stride for h in smem (conflict-free, 16B aligned)

// ---------------- device scratch (no cudaMalloc allowed) ----------------
__device__ float g_X[(size_t)L_ * B_ * N3];   // precomputed x-contributions, ~402MB
__device__ float g_z[B_ * H_];                // z gate for current step
__device__ float g_rh[B_ * H_];               // r*h for current step
__device__ unsigned g_count = 0;              // grid barrier arrival counter
__device__ unsigned g_gen   = 0;              // grid barrier generation (monotonic)

// ---------------- grid-wide sense barrier (all CTAs co-resident) ----------------
__device__ __forceinline__ void grid_barrier(unsigned target) {
    __syncthreads();
    __threadfence();
    if (threadIdx.x == 0) {
        if (atomicAdd(&g_count, 1u) == (unsigned)(NCTA - 1)) {
            g_count = 0u;
            __threadfence();
            atomicExch(&g_gen, target);
        } else {
            unsigned v;
            do {
                __nanosleep(64);
                asm volatile("ld.acquire.gpu.u32 %0, [%1];" : "=r"(v) : "l"(&g_gen) : "memory");
            } while ((int)(v - target) < 0);
        }
    }
    __syncthreads();
}

// ---------------- precompute GEMM: g_X[t][b][n] = x[b][t][:] . Wcat[n][512:768] ----------------
// C[m][n], m = b*2048 + t over M=65536, n over N=1536, K=256.
__global__ void __launch_bounds__(256) precompute_x_kernel(
    const float* __restrict__ x,
    const float* __restrict__ Wz,
    const float* __restrict__ Wr,
    const float* __restrict__ Ww)
{
    __shared__ float As[16][132];
    __shared__ float Bs[16][132];

    const int m0 = blockIdx.y * 128;
    const int n0 = blockIdx.x * 128;
    const int tid = threadIdx.x;
    const int ty = tid >> 4;   // 0..15
    const int tx = tid & 15;   // 0..15

    float acc[8][8];
#pragma unroll
    for (int i = 0; i < 8; i++)
#pragma unroll
        for (int j = 0; j < 8; j++) acc[i][j] = 0.f;

    for (int k0 = 0; k0 < 256; k0 += 16) {
        // load A tile (128 rows x 16 k), transposed into As[k][m]
#pragma unroll
        for (int q = tid; q < 512; q += 256) {
            int r  = q >> 2;
            int kq = (q & 3) << 2;
            float4 v = *(const float4*)(x + (size_t)(m0 + r) * 256 + k0 + kq);
            As[kq + 0][r] = v.x; As[kq + 1][r] = v.y;
            As[kq + 2][r] = v.z; As[kq + 3][r] = v.w;
        }
        // load B tile (128 n-rows x 16 k), transposed into Bs[k][n]
#pragma unroll
        for (int q = tid; q < 512; q += 256) {
            int r  = q >> 2;
            int kq = (q & 3) << 2;
            int n  = n0 + r;
            const float* wrow;
            if (n < 512)        wrow = Wz + (size_t)n * HX;
            else if (n < 1024)  wrow = Wr + (size_t)(n - 512) * HX;
            else                wrow = Ww + (size_t)(n - 1024) * HX;
            float4 v = *(const float4*)(wrow + 512 + k0 + kq);
            Bs[kq + 0][r] = v.x; Bs[kq + 1][r] = v.y;
            Bs[kq + 2][r] = v.z; Bs[kq + 3][r] = v.w;
        }
        __syncthreads();
#pragma unroll
        for (int kk = 0; kk < 16; kk++) {
            float a[8], b[8];
#pragma unroll
            for (int i = 0; i < 8; i++) a[i] = As[kk][ty * 8 + i];
#pragma unroll
            for (int j = 0; j < 8; j++) b[j] = Bs[kk][tx * 8 + j];
#pragma unroll
            for (int i = 0; i < 8; i++)
#pragma unroll
                for (int j = 0; j < 8; j++) acc[i][j] += a[i] * b[j];
        }
        __syncthreads();
    }

    // epilogue: scatter rows m=(b,t) -> g_X[(t*32+b)*1536 + n]
#pragma unroll
    for (int i = 0; i < 8; i++) {
        int m = m0 + ty * 8 + i;
        int t = m & 2047;
        int b = m >> 11;
        size_t base = ((size_t)t * B_ + b) * N3 + n0 + tx * 8;
        float4 v0 = make_float4(acc[i][0], acc[i][1], acc[i][2], acc[i][3]);
        float4 v1 = make_float4(acc[i][4], acc[i][5], acc[i][6], acc[i][7]);
        *(float4*)&g_X[base + 0] = v0;
        *(float4*)&g_X[base + 4] = v1;
    }
}

// ---------------- persistent recurrent kernel ----------------
// smem: h_s[32][516] | WA[8][516] | WB[4][516]   = 90816 bytes
#define SMEM_BYTES ((32 + 8 + 4) * HS * 4)

__global__ void __launch_bounds__(NTHR, 1) gru_persistent_kernel(
    const float* __restrict__ h0,
    const float* __restrict__ Wz,
    const float* __restrict__ Wr,
    const float* __restrict__ Ww,
    float* __restrict__ out)
{
    extern __shared__ float smem[];
    float* h_s = smem;                  // [32][HS]
    float* WA  = smem + 32 * HS;        // [8][HS]  (z/r weight rows, h-part)
    float* WB  = WA + 8 * HS;           // [4][HS]  (w weight rows, h-part)

    const int cta = blockIdx.x;
    const int tid = threadIdx.x;
    const int c0  = cta * 8;            // combined (z|r) column base, 0..1023
    const int j0  = cta * 4;            // w column base, 0..511

    // cache weight slices in smem (once for all 2048 steps)
    for (int q = tid; q < 8 * 128; q += NTHR) {          // 8 rows x 128 float4
        int rr = q >> 7, kq = (q & 127) << 2;
        int c  = c0 + rr;
        const float* src = (c < H_) ? (Wz + (size_t)c * HX)
                                    : (Wr + (size_t)(c - H_) * HX);
        *(float4*)&WA[rr * HS + kq] = *(const float4*)(src + kq);
    }
    for (int q = tid; q < 4 * 128; q += NTHR) {          // 4 rows x 128 float4
        int rr = q >> 7, kq = (q & 127) << 2;
        *(float4*)&WB[rr * HS + kq] = *(const float4*)(Ww + (size_t)(j0 + rr) * HX + kq);
    }

    unsigned gen0;
    asm volatile("ld.acquire.gpu.u32 %0, [%1];" : "=r"(gen0) : "l"(&g_gen) : "memory");

    const int w    = tid >> 5;
    const int lane = tid & 31;
    // phase A mapping: 8 cols x 32 batches per CTA; warp covers 8 cols x 4 batches
    const int ja = lane & 7;
    const int ba = 4 * w + (lane >> 3);
    // phase B mapping: 4 cols x 32 batches, warps 0..3; warp covers 4 cols x 8 batches
    const int jb = lane & 3;
    const int bb = 8 * w + (lane >> 2);

    for (int t = 0; t < L_; t++) {
        const float* hsrc = (t == 0) ? h0 : (out + (size_t)(t - 1) * B_ * H_);

        // stage h (bypass L1: written by other CTAs last step)
        for (int q = tid; q < B_ * H_ / 4; q += NTHR) {
            int f = q << 2;
            int b = f >> 9, k = f & 511;
            float4 v = __ldcg((const float4*)(hsrc + f));
            *(float4*)&h_s[b * HS + k] = v;
        }
        __syncthreads();

        // -------- phase A: z (ctas 0..63) / r & r*h (ctas 64..127) --------
        {
            const int c = c0 + ja;
            float xv = __ldg(&g_X[((size_t)t * B_ + ba) * N3 + c]);
            const float4* hp = (const float4*)&h_s[ba * HS];
            const float4* wp = (const float4*)&WA[ja * HS];
            float a0 = 0.f, a1 = 0.f, a2 = 0.f, a3 = 0.f;
#pragma unroll 8
            for (int kk = 0; kk < 128; kk++) {
                float4 hv = hp[kk];
                float4 wv = wp[kk];
                a0 += hv.x * wv.x; a1 += hv.y * wv.y;
                a2 += hv.z * wv.z; a3 += hv.w * wv.w;
            }
            float s = (a0 + a1) + (a2 + a3) + xv;
            float g = 1.f / (1.f + expf(-s));
            if (c < H_) g_z[ba * H_ + c] = g;
            else        g_rh[ba * H_ + (c - H_)] = g * h_s[ba * HS + (c - H_)];
        }
        grid_barrier(gen0 + (unsigned)(2 * t + 1));

        // stage r*h into the same smem buffer
        for (int q = tid; q < B_ * H_ / 4; q += NTHR) {
            int f = q << 2;
            int b = f >> 9, k = f & 511;
            float4 v = __ldcg((const float4*)(g_rh + f));
            *(float4*)&h_s[b * HS + k] = v;
        }
        __syncthreads();

        // -------- phase B: h_hat + blend (warps 0..3) --------
        if (w < 4) {
            const int j = j0 + jb;
            float xv = __ldg(&g_X[((size_t)t * B_ + bb) * N3 + 1024 + j]);
            const float4* hp = (const float4*)&h_s[bb * HS];
            const float4* wp = (const float4*)&WB[jb * HS];
            float a0 = 0.f, a1 = 0.f, a2 = 0.f, a3 = 0.f;
#pragma unroll 8
            for (int kk = 0; kk < 128; kk++) {
                float4 hv = hp[kk];
                float4 wv = wp[kk];
                a0 += hv.x * wv.x; a1 += hv.y * wv.y;
                a2 += hv.z * wv.z; a3 += hv.w * wv.w;
            }
            float hh    = tanhf((a0 + a1) + (a2 + a3) + xv);
            float hprev = __ldcg(hsrc + bb * H_ + j);
            float zv    = __ldcg(g_z + bb * H_ + j);
            out[((size_t)t * B_ + bb) * H_ + j] = hprev + zv * (hh - hprev);
        }
        grid_barrier(gen0 + (unsigned)(2 * t + 2));
    }
}

// ---------------- launch ----------------
extern "C" void kernel_launch(void* const* d_in, const int* in_sizes, int n_in,
                              void* d_out, int out_size)
{
    const float* x  = (const float*)d_in[0];   // [32, 2048, 256]
    const float* h0 = (const float*)d_in[1];   // [32, 512]
    const float* Wz = (const float*)d_in[2];   // [512, 768]
    const float* Wr = (const float*)d_in[3];   // [512, 768]
    const float* Ww = (const float*)d_in[4];   // [512, 768]
    float* out = (float*)d_out;                // [2048, 32, 512]

    cudaFuncSetAttribute(gru_persistent_kernel,
                         cudaFuncAttributeMaxDynamicSharedMemorySize, SMEM_BYTES);

    dim3 pgrid(N3 / 128, (B_ * L_) / 128);     // (12, 512)
    precompute_x_kernel<<<pgrid, 256>>>(x, Wz, Wr, Ww);

    gru_persistent_kernel<<<NCTA, NTHR, SMEM_BYTES>>>(h0, Wz, Wr, Ww, out);
}

// round 2
// speedup vs baseline: 1.4357x; 1.4357x over previous
#include <cuda_runtime.h>
#include <cstdint>
#include <math.h>

// Problem constants
#define B_    32
#define L_    2048
#define I_    256
#define H_    512
#define HX    768      // H + I (weight row length)
#define N3    1536     // 3*H combined gate columns (z | r | w)
#define NCTA  128
#define NTHR  256

// Grid partition: 16 column-groups x 8 batch-groups
#define NCG   16
#define NBG   8
#define BPG   4        // batches per group
#define CPG   32       // gate columns per group (per gate)

// ---------------- device scratch (no cudaMalloc allowed) ----------------
__device__ float g_X[(size_t)L_ * B_ * N3];     // precomputed x-contributions
__device__ float g_rh[B_ * H_];                 // r*h exchange (per step)
__device__ unsigned g_cnt[NBG * 32];            // per-group barrier counters (padded)
__device__ unsigned g_gen2[NBG * 32];           // per-group barrier generations

// ---------------- 16-CTA group barrier ----------------
__device__ __forceinline__ void group_barrier(int bg, unsigned target) {
    __syncthreads();
    __threadfence();
    if (threadIdx.x == 0) {
        unsigned* cnt = &g_cnt[bg * 32];
        unsigned* gen = &g_gen2[bg * 32];
        if (atomicAdd(cnt, 1u) == (unsigned)(NCG - 1)) {
            *cnt = 0u;
            __threadfence();
            atomicExch(gen, target);
        } else {
            unsigned v;
            do {
                asm volatile("ld.acquire.gpu.u32 %0, [%1];" : "=r"(v) : "l"(gen) : "memory");
            } while ((int)(v - target) < 0);
        }
    }
    __syncthreads();
}

// ---------------- precompute GEMM: g_X[t][b][n] = x[b][t][:] . Wcat[n][512:768] ----------------
__global__ void __launch_bounds__(256) precompute_x_kernel(
    const float* __restrict__ x,
    const float* __restrict__ Wz,
    const float* __restrict__ Wr,
    const float* __restrict__ Ww)
{
    __shared__ float As[16][132];
    __shared__ float Bs[16][132];

    const int m0 = blockIdx.y * 128;
    const int n0 = blockIdx.x * 128;
    const int tid = threadIdx.x;
    const int ty = tid >> 4;
    const int tx = tid & 15;

    float acc[8][8];
#pragma unroll
    for (int i = 0; i < 8; i++)
#pragma unroll
        for (int j = 0; j < 8; j++) acc[i][j] = 0.f;

    for (int k0 = 0; k0 < 256; k0 += 16) {
#pragma unroll
        for (int q = tid; q < 512; q += 256) {
            int r  = q >> 2;
            int kq = (q & 3) << 2;
            float4 v = *(const float4*)(x + (size_t)(m0 + r) * 256 + k0 + kq);
            As[kq + 0][r] = v.x; As[kq + 1][r] = v.y;
            As[kq + 2][r] = v.z; As[kq + 3][r] = v.w;
        }
#pragma unroll
        for (int q = tid; q < 512; q += 256) {
            int r  = q >> 2;
            int kq = (q & 3) << 2;
            int n  = n0 + r;
            const float* wrow;
            if (n < 512)        wrow = Wz + (size_t)n * HX;
            else if (n < 1024)  wrow = Wr + (size_t)(n - 512) * HX;
            else                wrow = Ww + (size_t)(n - 1024) * HX;
            float4 v = *(const float4*)(wrow + 512 + k0 + kq);
            Bs[kq + 0][r] = v.x; Bs[kq + 1][r] = v.y;
            Bs[kq + 2][r] = v.z; Bs[kq + 3][r] = v.w;
        }
        __syncthreads();
#pragma unroll
        for (int kk = 0; kk < 16; kk++) {
            float a[8], b[8];
#pragma unroll
            for (int i = 0; i < 8; i++) a[i] = As[kk][ty * 8 + i];
#pragma unroll
            for (int j = 0; j < 8; j++) b[j] = Bs[kk][tx * 8 + j];
#pragma unroll
            for (int i = 0; i < 8; i++)
#pragma unroll
                for (int j = 0; j < 8; j++) acc[i][j] += a[i] * b[j];
        }
        __syncthreads();
    }

#pragma unroll
    for (int i = 0; i < 8; i++) {
        int m = m0 + ty * 8 + i;
        int t = m & 2047;
        int b = m >> 11;
        size_t base = ((size_t)t * B_ + b) * N3 + n0 + tx * 8;
        *(float4*)&g_X[base + 0] = make_float4(acc[i][0], acc[i][1], acc[i][2], acc[i][3]);
        *(float4*)&g_X[base + 4] = make_float4(acc[i][4], acc[i][5], acc[i][6], acc[i][7]);
    }
}

// ---------------- persistent recurrent kernel ----------------
// smem: WA[64][512] | WB[32][512] | h_s[4][512] | rh_s[4][512] | z_s[4][32]
#define SM_WA   0
#define SM_WB   (64 * 512)
#define SM_H    (SM_WB + 32 * 512)
#define SM_RH   (SM_H + 4 * 512)
#define SM_Z    (SM_RH + 4 * 512)
#define SMEM_FLOATS (SM_Z + 4 * 32)
#define SMEM_BYTES  (SMEM_FLOATS * 4)

__global__ void __launch_bounds__(NTHR, 1) gru_persistent_kernel(
    const float* __restrict__ h0,
    const float* __restrict__ Wz,
    const float* __restrict__ Wr,
    const float* __restrict__ Ww,
    float* __restrict__ out)
{
    extern __shared__ float sm[];
    float*  WA   = sm + SM_WA;    // 64 rows (32 Wz | 32 Wr) x 512
    float*  WB   = sm + SM_WB;    // 32 rows (Ww) x 512
    float*  h_s  = sm + SM_H;     // 4 x 512
    float*  rh_s = sm + SM_RH;    // 4 x 512
    float*  z_s  = sm + SM_Z;     // 4 x 32

    const int cta = blockIdx.x;
    const int tid = threadIdx.x;
    const int cg  = cta & (NCG - 1);   // column group 0..15
    const int bg  = cta >> 4;          // batch group 0..7
    const int b0  = bg * BPG;          // first global batch
    const int c0  = cg * CPG;          // first gate column (per gate)

    // ---- cache weight slices in smem (once for all steps) ----
    for (int q = tid; q < 64 * 128; q += NTHR) {       // float4 granularity
        int row = q >> 7, k4 = q & 127;
        const float* src = (row < 32) ? (Wz + (size_t)(c0 + row) * HX)
                                      : (Wr + (size_t)(c0 + row - 32) * HX);
        ((float4*)WA)[row * 128 + k4] = ((const float4*)src)[k4];
    }
    for (int q = tid; q < 32 * 128; q += NTHR) {
        int row = q >> 7, k4 = q & 127;
        ((float4*)WB)[row * 128 + k4] = ((const float4*)(Ww + (size_t)(c0 + row) * HX))[k4];
    }

    unsigned gen0;
    asm volatile("ld.acquire.gpu.u32 %0, [%1];" : "=r"(gen0) : "l"(&g_gen2[bg * 32]) : "memory");

    // phase A mapping: 16 col-tiles (4 cols each) x 16 k-splits
    const int ct  = tid >> 4;          // col-tile 0..15 (0-7 -> z, 8-15 -> r)
    const int ks  = tid & 15;          // k-split lane
    // phase B mapping: 8 col-tiles x 32 k-splits
    const int ct2 = tid >> 5;          // 0..7
    const int ks2 = tid & 31;

    const float4* h4  = (const float4*)h_s;
    const float4* rh4 = (const float4*)rh_s;

    for (int t = 0; t < L_; t++) {
        const float* hsrc = (t == 0) ? h0 : (out + (size_t)(t - 1) * B_ * H_);

        // ---- stage h for our 4 batches (bypass L1) ----
        for (int q = tid; q < 4 * 128; q += NTHR) {
            int b = q >> 7, k4 = q & 127;
            ((float4*)h_s)[q] = __ldcg(((const float4*)(hsrc + (size_t)(b0 + b) * H_)) + k4);
        }
        __syncthreads();

        // -------- phase A: z and r gates (4 batches x 64 cols) --------
        {
            const int lb = ks >> 2, lc = ks & 3;       // output element this lane emits
            const int colIdx = ct * 4 + lc;            // 0..63 local
            const int isZ = (colIdx < 32);
            const int gcol = isZ ? (c0 + colIdx) : (H_ + c0 + colIdx - 32);
            float xv = __ldg(&g_X[((size_t)t * B_ + b0 + lb) * N3 + gcol]);

            float acc[4][4];
#pragma unroll
            for (int i = 0; i < 4; i++)
#pragma unroll
                for (int j = 0; j < 4; j++) acc[i][j] = 0.f;

            const float4* w4 = (const float4*)WA + (ct * 4) * 128;
#pragma unroll
            for (int j = 0; j < 8; j++) {
                int kk = j * 16 + ks;                  // interleaved k-chunks: conflict-free
                float4 hv0 = h4[0 * 128 + kk];
                float4 hv1 = h4[1 * 128 + kk];
                float4 hv2 = h4[2 * 128 + kk];
                float4 hv3 = h4[3 * 128 + kk];
#pragma unroll
                for (int c = 0; c < 4; c++) {
                    float4 wv = w4[c * 128 + kk];
                    acc[0][c] = fmaf(hv0.x, wv.x, fmaf(hv0.y, wv.y, fmaf(hv0.z, wv.z, fmaf(hv0.w, wv.w, acc[0][c]))));
                    acc[1][c] = fmaf(hv1.x, wv.x, fmaf(hv1.y, wv.y, fmaf(hv1.z, wv.z, fmaf(hv1.w, wv.w, acc[1][c]))));
                    acc[2][c] = fmaf(hv2.x, wv.x, fmaf(hv2.y, wv.y, fmaf(hv2.z, wv.z, fmaf(hv2.w, wv.w, acc[2][c]))));
                    acc[3][c] = fmaf(hv3.x, wv.x, fmaf(hv3.y, wv.y, fmaf(hv3.z, wv.z, fmaf(hv3.w, wv.w, acc[3][c]))));
                }
            }
            // 16-way cross-lane reduction (stays within 16-lane groups)
#pragma unroll
            for (int m = 1; m <= 8; m <<= 1)
#pragma unroll
                for (int i = 0; i < 4; i++)
#pragma unroll
                    for (int j = 0; j < 4; j++)
                        acc[i][j] += __shfl_xor_sync(0xffffffffu, acc[i][j], m);

            float s = acc[0][0];
#pragma unroll
            for (int i = 1; i < 16; i++)
                if (ks == i) s = acc[i >> 2][i & 3];
            s += xv;
            float g = 1.f / (1.f + expf(-s));
            if (isZ) {
                z_s[lb * 32 + colIdx] = g;
            } else {
                int kcol = c0 + colIdx - 32;           // h column this r gate multiplies
                g_rh[(size_t)(b0 + lb) * H_ + kcol] = g * h_s[lb * H_ + kcol];
            }
        }
        group_barrier(bg, gen0 + (unsigned)(2 * t + 1));

        // ---- stage r*h for our 4 batches ----
        for (int q = tid; q < 4 * 128; q += NTHR) {
            int b = q >> 7, k4 = q & 127;
            ((float4*)rh_s)[q] = __ldcg(((const float4*)(g_rh + (size_t)(b0 + b) * H_)) + k4);
        }
        __syncthreads();

        // -------- phase B: candidate + blend (4 batches x 32 cols) --------
        {
            const int lb = (ks2 & 15) >> 2, lc = ks2 & 3;
            const int jloc = ct2 * 4 + lc;             // 0..31 local w col
            const int jglob = c0 + jloc;
            float xv = 0.f;
            if (ks2 < 16) xv = __ldg(&g_X[((size_t)t * B_ + b0 + lb) * N3 + 1024 + jglob]);

            float acc[4][4];
#pragma unroll
            for (int i = 0; i < 4; i++)
#pragma unroll
                for (int j = 0; j < 4; j++) acc[i][j] = 0.f;

            const float4* w4 = (const float4*)WB + (ct2 * 4) * 128;
#pragma unroll
            for (int j = 0; j < 4; j++) {
                int kk = j * 32 + ks2;
                float4 hv0 = rh4[0 * 128 + kk];
                float4 hv1 = rh4[1 * 128 + kk];
                float4 hv2 = rh4[2 * 128 + kk];
                float4 hv3 = rh4[3 * 128 + kk];
#pragma unroll
                for (int c = 0; c < 4; c++) {
                    float4 wv = w4[c * 128 + kk];
                    acc[0][c] = fmaf(hv0.x, wv.x, fmaf(hv0.y, wv.y, fmaf(hv0.z, wv.z, fmaf(hv0.w, wv.w, acc[0][c]))));
                    acc[1][c] = fmaf(hv1.x, wv.x, fmaf(hv1.y, wv.y, fmaf(hv1.z, wv.z, fmaf(hv1.w, wv.w, acc[1][c]))));
                    acc[2][c] = fmaf(hv2.x, wv.x, fmaf(hv2.y, wv.y, fmaf(hv2.z, wv.z, fmaf(hv2.w, wv.w, acc[2][c]))));
                    acc[3][c] = fmaf(hv3.x, wv.x, fmaf(hv3.y, wv.y, fmaf(hv3.z, wv.z, fmaf(hv3.w, wv.w, acc[3][c]))));
                }
            }
#pragma unroll
            for (int m = 1; m <= 16; m <<= 1)
#pragma unroll
                for (int i = 0; i < 4; i++)
#pragma unroll
                    for (int j = 0; j < 4; j++)
                        acc[i][j] += __shfl_xor_sync(0xffffffffu, acc[i][j], m);

            if (ks2 < 16) {
                float s = acc[0][0];
#pragma unroll
                for (int i = 1; i < 16; i++)
                    if (ks2 == i) s = acc[i >> 2][i & 3];
                s += xv;
                float hh    = tanhf(s);
                float hprev = h_s[lb * H_ + jglob];
                float zv    = z_s[lb * 32 + jloc];
                out[((size_t)t * B_ + b0 + lb) * H_ + jglob] = hprev + zv * (hh - hprev);
            }
        }
        group_barrier(bg, gen0 + (unsigned)(2 * t + 2));
    }
}

// ---------------- launch ----------------
extern "C" void kernel_launch(void* const* d_in, const int* in_sizes, int n_in,
                              void* d_out, int out_size)
{
    const float* x  = (const float*)d_in[0];   // [32, 2048, 256]
    const float* h0 = (const float*)d_in[1];   // [32, 512]
    const float* Wz = (const float*)d_in[2];   // [512, 768]
    const float* Wr = (const float*)d_in[3];   // [512, 768]
    const float* Ww = (const float*)d_in[4];   // [512, 768]
    float* out = (float*)d_out;                // [2048, 32, 512]

    cudaFuncSetAttribute(gru_persistent_kernel,
                         cudaFuncAttributeMaxDynamicSharedMemorySize, SMEM_BYTES);

    dim3 pgrid(N3 / 128, (B_ * L_) / 128);     // (12, 512)
    precompute_x_kernel<<<pgrid, 256>>>(x, Wz, Wr, Ww);

    gru_persistent_kernel<<<NCTA, NTHR, SMEM_BYTES>>>(h0, Wz, Wr, Ww, out);
}